// round 4
// baseline (speedup 1.0000x reference)
#include <cuda_runtime.h>
#include <cstdint>
#include <cstddef>

#define T_TOTAL 524288
#define NCHUNK  1024
#define CHUNK_L 512
#define TILE_R  64
#define NTILES  8

// chunk-level scan state (tiny)
__device__ __align__(16) float g_Ac[NCHUNK * 64];
__device__ __align__(16) float g_Bc[NCHUNK * 64];
__device__ __align__(16) float g_U [NCHUNK * 64];

typedef unsigned long long u64;

__device__ __forceinline__ u64 pk2(float lo, float hi) {
    u64 r; asm("mov.b64 %0, {%1,%2};" : "=l"(r) : "f"(lo), "f"(hi)); return r;
}
__device__ __forceinline__ float2 upk(u64 v) {
    float2 r; asm("mov.b64 {%0,%1}, %2;" : "=f"(r.x), "=f"(r.y) : "l"(v)); return r;
}
// packed fp32x2 FMA (Blackwell FFMA2): d += a*b per lane
__device__ __forceinline__ void ffma2(u64 &d, u64 a, u64 b) {
    asm("fma.rn.f32x2 %0, %1, %2, %0;" : "+l"(d) : "l"(a), "l"(b));
}
__device__ __forceinline__ float sigf(float x) {
    float e = __expf(-x);
    return __fdividef(1.0f, 1.0f + e);
}

// ----------------------------------------------------------------------------
// Swizzled transposed x tile: float4 block (k, rb) stored at  k*16 + (rb ^ (k&15))
// -> GEMM loads are LDS.128 broadcast, fill stores are conflict-free.
// ----------------------------------------------------------------------------
__device__ __forceinline__ void fill_x(float* xsf, const float* __restrict__ inp,
                                       int t0, int tid) {
    #pragma unroll
    for (int p = 0; p < 4; p++) {
        int i = tid + p * 256;
        int r = i >> 4, c = i & 15;
        float4 v = *(const float4*)(inp + (size_t)(t0 + r) * 64 + 4 * c);
        int rb = r >> 2, r3 = r & 3;
        #pragma unroll
        for (int j = 0; j < 4; j++) {
            int k = 4 * c + j;
            float val = (j == 0) ? v.x : (j == 1) ? v.y : (j == 2) ? v.z : v.w;
            xsf[(k * 16 + (rb ^ (k & 15))) * 4 + r3] = val;
        }
    }
}

// GEMM1 tile core: 8 rows (4 packed pairs) x 4 channels per thread.
// 3 LDS per k (2x LDS.128 broadcast x, 1x LDS.128 interleaved w), 16 FFMA2.
__device__ __forceinline__ void gemm1_core(const float4* xs4, const float4* w4,
                                           int ri, int ci,
                                           u64 aL0[4], u64 aL1[4],
                                           u64 aR0[4], u64 aR1[4]) {
    const int rb0 = 2 * ri, rb1 = 2 * ri + 1;
    #pragma unroll
    for (int q = 0; q < 4; q++) { aL0[q] = 0ull; aL1[q] = 0ull; aR0[q] = 0ull; aR1[q] = 0ull; }
    #pragma unroll 1
    for (int k0 = 0; k0 < 64; k0 += 16) {
        #pragma unroll
        for (int j = 0; j < 16; j++) {
            const int k = k0 + j;
            ulonglong2 xA = *(const ulonglong2*)(xs4 + k * 16 + (rb0 ^ j));
            ulonglong2 xB = *(const ulonglong2*)(xs4 + k * 16 + (rb1 ^ j));
            float4 wv = w4[k * 32 + ci];
            u64 wl0 = pk2(wv.x, wv.x), wl1 = pk2(wv.y, wv.y);
            u64 wr0 = pk2(wv.z, wv.z), wr1 = pk2(wv.w, wv.w);
            ffma2(aL0[0], xA.x, wl0); ffma2(aL0[1], xA.y, wl0);
            ffma2(aL0[2], xB.x, wl0); ffma2(aL0[3], xB.y, wl0);
            ffma2(aL1[0], xA.x, wl1); ffma2(aL1[1], xA.y, wl1);
            ffma2(aL1[2], xB.x, wl1); ffma2(aL1[3], xB.y, wl1);
            ffma2(aR0[0], xA.x, wr0); ffma2(aR0[1], xA.y, wr0);
            ffma2(aR0[2], xB.x, wr0); ffma2(aR0[3], xB.y, wr0);
            ffma2(aR1[0], xA.x, wr1); ffma2(aR1[1], xA.y, wr1);
            ffma2(aR1[2], xB.x, wr1); ffma2(aR1[3], xB.y, wr1);
        }
    }
}

// build interleaved W1 in smem: W1i4[k*32+ci] = {W1[k][2ci],W1[k][2ci+1],W1[k][64+2ci],W1[k][64+2ci+1]}
__device__ __forceinline__ void build_w1i(float4* W1i4, const float* __restrict__ W1, int tid) {
    #pragma unroll
    for (int p = 0; p < 8; p++) {
        int idx = tid + p * 256;
        int k = idx >> 5, cc = idx & 31;
        float2 l = *(const float2*)(W1 + k * 128 + 2 * cc);
        float2 r = *(const float2*)(W1 + k * 128 + 64 + 2 * cc);
        W1i4[idx] = make_float4(l.x, l.y, r.x, r.y);
    }
}

// ============================================================================
// Kernel 1: GEMM1 + sigmoid + gate + hierarchical chunk compose (no row stores)
// smem = 53248 B, 3 CTAs/SM
// ============================================================================
__global__ __launch_bounds__(256, 3)
void k1_gemm1_compose(const float* __restrict__ inp,
                      const float* __restrict__ W1,
                      const float* __restrict__ B1) {
    extern __shared__ float sm[];
    float4* W1i4  = (float4*)sm;                      // 32768 B
    float*  xsf   = sm + 8192;                        // 16384 B (swizzled x)
    float2* parts = (float2*)(sm + 8192 + 4096);      // 4096 B (8 groups x 64 ch)

    const int tid = threadIdx.x, c = blockIdx.x;
    const int ri = tid >> 5, ci = tid & 31;

    build_w1i(W1i4, W1, tid);
    const float bl0 = B1[2 * ci],      bl1 = B1[2 * ci + 1];
    const float br0 = B1[64 + 2 * ci], br1 = B1[64 + 2 * ci + 1];

    float Av = 1.0f, Bv = 0.0f;        // running chunk affine (threads 0..63)
    __syncthreads();

    for (int tt = 0; tt < NTILES; tt++) {
        const int t0 = c * CHUNK_L + tt * TILE_R;
        fill_x(xsf, inp, t0, tid);
        __syncthreads();

        u64 aL0[4], aL1[4], aR0[4], aR1[4];
        gemm1_core((const float4*)xsf, W1i4, ri, ci, aL0, aL1, aR0, aR1);

        // epilogue: gate + in-register compose over this thread's 8 rows (time order)
        float A0 = 1.f, B0 = 0.f, A1 = 1.f, B1v = 0.f;
        #pragma unroll
        for (int p2 = 0; p2 < 4; p2++) {
            float2 L0 = upk(aL0[p2]), L1 = upk(aL1[p2]);
            float2 R0 = upk(aR0[p2]), R1 = upk(aR1[p2]);
            #pragma unroll
            for (int e = 0; e < 2; e++) {
                float l0 = sigf((e ? L0.y : L0.x) + bl0);
                float l1 = sigf((e ? L1.y : L1.x) + bl1);
                float r0 = sigf((e ? R0.y : R0.x) + br0);
                float r1 = sigf((e ? R1.y : R1.x) + br1);
                float a0 = l0 * r0, b0 = 1.f - l0;
                float a1 = l1 * r1, b1 = 1.f - l1;
                B0  = fmaf(a0, B0, b0);  A0 *= a0;
                B1v = fmaf(a1, B1v, b1); A1 *= a1;
            }
        }
        ((float4*)parts)[ri * 32 + ci] = make_float4(A0, B0, A1, B1v);
        __syncthreads();

        if (tid < 64) {   // combine 8 row-group partials in order
            #pragma unroll
            for (int g = 0; g < 8; g++) {
                float2 pp = parts[g * 64 + tid];
                Bv = fmaf(pp.x, Bv, pp.y);
                Av *= pp.x;
            }
        }
    }
    if (tid < 64) { g_Ac[c * 64 + tid] = Av; g_Bc[c * 64 + tid] = Bv; }
}

// ============================================================================
// Kernel 2: sequential prefix over 1024 chunks
// ============================================================================
__global__ void k2_chunk_scan() {
    const int j = threadIdx.x;
    float u = 0.0f;
    #pragma unroll 4
    for (int cc = 0; cc < NCHUNK; cc++) {
        g_U[cc * 64 + j] = u;
        u = fmaf(g_Ac[cc * 64 + j], u, g_Bc[cc * 64 + j]);
    }
}

// ============================================================================
// Kernel 3: recompute GEMM1 -> a,b in registers -> hierarchical in-tile scan
//           -> z into swizzled tile (unioned with x) -> GEMM2 -> out.
// smem = 71680 B, 3 CTAs/SM
// ============================================================================
__global__ __launch_bounds__(256, 3)
void k3_recompute_gemm2(const float* __restrict__ inp,
                        const float* __restrict__ W1,
                        const float* __restrict__ B1,
                        const float* __restrict__ W2,
                        const float* __restrict__ B2,
                        float* __restrict__ out) {
    extern __shared__ float sm[];
    float4* W1i4  = (float4*)sm;                    // [0, 32768) B
    float*  xsf   = sm + 8192;                      // [32768, 49152) B  (x tile, reused for z)
    float2* parts = (float2*)(sm + 12288);          // [49152, 53248) B
    float*  ust   = sm + 13312;                     // [53248, 55296) B  (u at group starts)
    u64*    W2d   = (u64*)(sm + 13824);             // [55296, 71680) B  (duplicated W2)

    const int tid = threadIdx.x, c = blockIdx.x;
    const int ri = tid >> 5, ci = tid & 31;
    const int oc = tid & 31, rp = tid >> 5;

    build_w1i(W1i4, W1, tid);
    #pragma unroll
    for (int p = 0; p < 8; p++) {       // W2d[k*32+oc] = {w,w}
        int idx = tid + p * 256;
        float w = W2[idx];
        W2d[idx] = pk2(w, w);
    }
    const float bl0 = B1[2 * ci],      bl1 = B1[2 * ci + 1];
    const float br0 = B1[64 + 2 * ci], br1 = B1[64 + 2 * ci + 1];
    const float b2  = B2[oc];
    if (c == 0 && tid < 32) out[tid] = B2[tid];     // row 0: z = 0

    float uc = 0.0f;
    if (tid < 64) uc = g_U[c * 64 + tid];           // chunk-start state
    __syncthreads();

    for (int tt = 0; tt < NTILES; tt++) {
        const int t0 = c * CHUNK_L + tt * TILE_R;
        fill_x(xsf, inp, t0, tid);
        __syncthreads();

        u64 aL0[4], aL1[4], aR0[4], aR1[4];
        gemm1_core((const float4*)xsf, W1i4, ri, ci, aL0, aL1, aR0, aR1);

        // epilogue: gate -> a,b kept in registers; compose row-group partial
        float av0[8], bv0[8], av1[8], bv1[8];
        float A0 = 1.f, B0 = 0.f, A1 = 1.f, B1v = 0.f;
        #pragma unroll
        for (int p2 = 0; p2 < 4; p2++) {
            float2 L0 = upk(aL0[p2]), L1 = upk(aL1[p2]);
            float2 R0 = upk(aR0[p2]), R1 = upk(aR1[p2]);
            #pragma unroll
            for (int e = 0; e < 2; e++) {
                int idx = 2 * p2 + e;
                float l0 = sigf((e ? L0.y : L0.x) + bl0);
                float l1 = sigf((e ? L1.y : L1.x) + bl1);
                float r0 = sigf((e ? R0.y : R0.x) + br0);
                float r1 = sigf((e ? R1.y : R1.x) + br1);
                float a0 = l0 * r0, b0 = 1.f - l0;
                float a1 = l1 * r1, b1 = 1.f - l1;
                av0[idx] = a0; bv0[idx] = b0;
                av1[idx] = a1; bv1[idx] = b1;
                B0  = fmaf(a0, B0, b0);  A0 *= a0;
                B1v = fmaf(a1, B1v, b1); A1 *= a1;
            }
        }
        ((float4*)parts)[ri * 32 + ci] = make_float4(A0, B0, A1, B1v);
        __syncthreads();

        // group prefix: u at start of each 8-row group (threads 0..63)
        if (tid < 64) {
            float u = uc;
            #pragma unroll
            for (int g = 0; g < 8; g++) {
                ust[g * 64 + tid] = u;
                float2 pp = parts[g * 64 + tid];
                u = fmaf(pp.x, u, pp.y);
            }
            uc = u;
        }
        __syncthreads();

        // replay in registers, write z transposed+swizzled into xsf (x no longer needed)
        {
            float2 us = *(const float2*)(ust + ri * 64 + 2 * ci);
            float u0 = us.x, u1 = us.y;
            const int j0 = 2 * ci, j1 = 2 * ci + 1;
            #pragma unroll
            for (int e = 0; e < 8; e++) {
                u0 = fmaf(av0[e], u0, bv0[e]);
                u1 = fmaf(av1[e], u1, bv1[e]);
                int r = 8 * ri + e;
                xsf[(j0 * 16 + ((r >> 2) ^ (j0 & 15))) * 4 + (r & 3)] = u0;
                xsf[(j1 * 16 + ((r >> 2) ^ (j1 & 15))) * 4 + (r & 3)] = u1;
            }
        }
        __syncthreads();

        // GEMM2: 8 rows (4 packed pairs) x 1 out-channel per thread
        u64 acc0 = pk2(b2, b2), acc1 = acc0, acc2 = acc0, acc3 = acc0;
        {
            const int rb0 = 2 * rp, rb1 = 2 * rp + 1;
            const float4* zs4 = (const float4*)xsf;
            #pragma unroll 1
            for (int k0 = 0; k0 < 64; k0 += 16) {
                #pragma unroll
                for (int j = 0; j < 16; j++) {
                    const int k = k0 + j;
                    ulonglong2 zA = *(const ulonglong2*)(zs4 + k * 16 + (rb0 ^ j));
                    ulonglong2 zB = *(const ulonglong2*)(zs4 + k * 16 + (rb1 ^ j));
                    u64 wd = W2d[k * 32 + oc];
                    ffma2(acc0, zA.x, wd); ffma2(acc1, zA.y, wd);
                    ffma2(acc2, zB.x, wd); ffma2(acc3, zB.y, wd);
                }
            }
        }
        #pragma unroll
        for (int q = 0; q < 4; q++) {
            u64 a = (q == 0) ? acc0 : (q == 1) ? acc1 : (q == 2) ? acc2 : acc3;
            float2 v = upk(a);
            int t = t0 + 1 + 8 * rp + 2 * q;
            if (t < T_TOTAL)     out[(size_t)t * 32 + oc]       = v.x;
            if (t + 1 < T_TOTAL) out[(size_t)(t + 1) * 32 + oc] = v.y;
        }
        __syncthreads();
    }
}

// ============================================================================
// launch
// ============================================================================
extern "C" void kernel_launch(void* const* d_in, const int* in_sizes, int n_in,
                              void* d_out, int out_size) {
    const float* inp = (const float*)d_in[0];
    const float* W1  = (const float*)d_in[1];
    const float* B1  = (const float*)d_in[2];
    const float* W2  = (const float*)d_in[3];
    const float* B2  = (const float*)d_in[4];
    float* out = (float*)d_out;

    const int smem1 = 53248;
    const int smem3 = 71680;
    cudaFuncSetAttribute(k1_gemm1_compose,   cudaFuncAttributeMaxDynamicSharedMemorySize, smem1);
    cudaFuncSetAttribute(k3_recompute_gemm2, cudaFuncAttributeMaxDynamicSharedMemorySize, smem3);

    k1_gemm1_compose<<<NCHUNK, 256, smem1>>>(inp, W1, B1);
    k2_chunk_scan<<<1, 64>>>();
    k3_recompute_gemm2<<<NCHUNK, 256, smem3>>>(inp, W1, B1, W2, B2, out);
    (void)in_sizes; (void)n_in; (void)out_size;
}

// round 7
// speedup vs baseline: 2.0431x; 2.0431x over previous
#include <cuda_runtime.h>
#include <cstdint>
#include <cstddef>

#define T_TOTAL 524288
#define NCHUNK  8192          // 64-row chunks
#define K1_BLK  4096          // k1: 128 rows (2 tiles) per CTA
#define TILE_R  64
#define SUPER   128           // chunks per super-chunk in k2
#define NSUPER  (NCHUNK / SUPER)

// packed per-row gate params: {a0,a1,b0,b1} for channel pair ci -> 268MB
__device__ __align__(16) float4 g_ab[(size_t)T_TOTAL * 32];
// per-chunk aggregates and chunk-start states
__device__ __align__(16) float g_Ac[NCHUNK * 64];
__device__ __align__(16) float g_Bc[NCHUNK * 64];
__device__ __align__(16) float g_U [NCHUNK * 64];
__device__ __align__(16) float g_A2[NSUPER * 64];
__device__ __align__(16) float g_B2[NSUPER * 64];
__device__ __align__(16) float g_U2[NSUPER * 64];

typedef unsigned long long u64;

__device__ __forceinline__ u64 pk2(float lo, float hi) {
    u64 r; asm("mov.b64 %0, {%1,%2};" : "=l"(r) : "f"(lo), "f"(hi)); return r;
}
__device__ __forceinline__ float2 upk(u64 v) {
    float2 r; asm("mov.b64 {%0,%1}, %2;" : "=f"(r.x), "=f"(r.y) : "l"(v)); return r;
}
__device__ __forceinline__ void ffma2(u64 &d, u64 a, u64 b) {
    asm("fma.rn.f32x2 %0, %1, %2, %0;" : "+l"(d) : "l"(a), "l"(b));
}
__device__ __forceinline__ float sigf(float x) {
    float e = __expf(-x);
    return __fdividef(1.0f, 1.0f + e);
}

// swizzled transposed x tile: float4 block (k, rb) at k*16 + (rb ^ (k&15))
__device__ __forceinline__ void fill_x(float* xsf, const float* __restrict__ inp,
                                       int t0, int tid) {
    #pragma unroll
    for (int p = 0; p < 4; p++) {
        int i = tid + p * 256;
        int r = i >> 4, c = i & 15;
        float4 v = *(const float4*)(inp + (size_t)(t0 + r) * 64 + 4 * c);
        int rb = r >> 2, r3 = r & 3;
        #pragma unroll
        for (int j = 0; j < 4; j++) {
            int k = 4 * c + j;
            float val = (j == 0) ? v.x : (j == 1) ? v.y : (j == 2) ? v.z : v.w;
            xsf[(k * 16 + (rb ^ (k & 15))) * 4 + r3] = val;
        }
    }
}

// GEMM1 core: 8 rows (4 packed pairs) x 4 channels per thread
__device__ __forceinline__ void gemm1_core(const float4* xs4, const float4* w4,
                                           int ri, int ci,
                                           u64 aL0[4], u64 aL1[4],
                                           u64 aR0[4], u64 aR1[4]) {
    const int rb0 = 2 * ri, rb1 = 2 * ri + 1;
    #pragma unroll
    for (int q = 0; q < 4; q++) { aL0[q]=0ull; aL1[q]=0ull; aR0[q]=0ull; aR1[q]=0ull; }
    #pragma unroll 1
    for (int k0 = 0; k0 < 64; k0 += 16) {
        #pragma unroll
        for (int j = 0; j < 16; j++) {
            const int k = k0 + j;
            ulonglong2 xA = *(const ulonglong2*)(xs4 + k * 16 + (rb0 ^ j));
            ulonglong2 xB = *(const ulonglong2*)(xs4 + k * 16 + (rb1 ^ j));
            float4 wv = w4[k * 32 + ci];
            u64 wl0 = pk2(wv.x, wv.x), wl1 = pk2(wv.y, wv.y);
            u64 wr0 = pk2(wv.z, wv.z), wr1 = pk2(wv.w, wv.w);
            ffma2(aL0[0], xA.x, wl0); ffma2(aL0[1], xA.y, wl0);
            ffma2(aL0[2], xB.x, wl0); ffma2(aL0[3], xB.y, wl0);
            ffma2(aL1[0], xA.x, wl1); ffma2(aL1[1], xA.y, wl1);
            ffma2(aL1[2], xB.x, wl1); ffma2(aL1[3], xB.y, wl1);
            ffma2(aR0[0], xA.x, wr0); ffma2(aR0[1], xA.y, wr0);
            ffma2(aR0[2], xB.x, wr0); ffma2(aR0[3], xB.y, wr0);
            ffma2(aR1[0], xA.x, wr1); ffma2(aR1[1], xA.y, wr1);
            ffma2(aR1[2], xB.x, wr1); ffma2(aR1[3], xB.y, wr1);
        }
    }
}

__device__ __forceinline__ void build_w1i(float4* W1i4, const float* __restrict__ W1, int tid) {
    #pragma unroll
    for (int p = 0; p < 8; p++) {
        int idx = tid + p * 256;
        int k = idx >> 5, cc = idx & 31;
        float2 l = *(const float2*)(W1 + k * 128 + 2 * cc);
        float2 r = *(const float2*)(W1 + k * 128 + 64 + 2 * cc);
        W1i4[idx] = make_float4(l.x, l.y, r.x, r.y);
    }
}

// ============================================================================
// k1: GEMM1 + gate -> g_ab (packed) + per-64-row-chunk aggregates
// smem = 53248 B, 3 CTAs/SM; 2 tiles per CTA
// ============================================================================
__global__ __launch_bounds__(256, 3)
void k1_gemm1(const float* __restrict__ inp,
              const float* __restrict__ W1,
              const float* __restrict__ B1) {
    extern __shared__ float sm[];
    float4* W1i4  = (float4*)sm;                 // [0,32768)
    float*  xsf   = sm + 8192;                   // [32768,49152)
    float2* parts = (float2*)(sm + 12288);       // [49152,53248)

    const int tid = threadIdx.x, c = blockIdx.x;
    const int ri = tid >> 5, ci = tid & 31;

    build_w1i(W1i4, W1, tid);
    const float bl0 = B1[2 * ci],      bl1 = B1[2 * ci + 1];
    const float br0 = B1[64 + 2 * ci], br1 = B1[64 + 2 * ci + 1];
    __syncthreads();

    #pragma unroll 1
    for (int tt = 0; tt < 2; tt++) {
        const int chunk = 2 * c + tt;
        const int t0 = chunk * TILE_R;
        fill_x(xsf, inp, t0, tid);
        __syncthreads();

        u64 aL0[4], aL1[4], aR0[4], aR1[4];
        gemm1_core((const float4*)xsf, W1i4, ri, ci, aL0, aL1, aR0, aR1);

        // gate -> store packed a,b; per-thread 8-row affine partial
        float A0 = 1.f, B0 = 0.f, A1 = 1.f, B1v = 0.f;
        #pragma unroll
        for (int p2 = 0; p2 < 4; p2++) {
            float2 L0 = upk(aL0[p2]), L1 = upk(aL1[p2]);
            float2 R0 = upk(aR0[p2]), R1 = upk(aR1[p2]);
            #pragma unroll
            for (int e = 0; e < 2; e++) {
                int r = 8 * ri + 2 * p2 + e;
                float l0 = sigf((e ? L0.y : L0.x) + bl0);
                float l1 = sigf((e ? L1.y : L1.x) + bl1);
                float r0 = sigf((e ? R0.y : R0.x) + br0);
                float r1 = sigf((e ? R1.y : R1.x) + br1);
                float a0 = l0 * r0, b0 = 1.f - l0;
                float a1 = l1 * r1, b1 = 1.f - l1;
                g_ab[(size_t)(t0 + r) * 32 + ci] = make_float4(a0, a1, b0, b1);
                B0  = fmaf(a0, B0, b0);  A0 *= a0;
                B1v = fmaf(a1, B1v, b1); A1 *= a1;
            }
        }
        ((float4*)parts)[ri * 32 + ci] = make_float4(A0, B0, A1, B1v);
        __syncthreads();

        if (tid < 64) {   // combine 8 row-group partials (time order) -> chunk aggregate
            float Ac = 1.f, Bc = 0.f;
            #pragma unroll
            for (int g = 0; g < 8; g++) {
                float2 pp = parts[g * 64 + tid];
                Bc = fmaf(pp.x, Bc, pp.y);
                Ac *= pp.x;
            }
            g_Ac[chunk * 64 + tid] = Ac;
            g_Bc[chunk * 64 + tid] = Bc;
        }
        __syncthreads();
    }
}

// ============================================================================
// k2: hierarchical chunk scan (8192 chunks = 64 supers x 128)
// ============================================================================
__global__ void k2a_super_agg() {          // grid 64, block 64
    const int s = blockIdx.x, j = threadIdx.x;
    float A = 1.f, B = 0.f;
    #pragma unroll 4
    for (int i = 0; i < SUPER; i++) {
        int c = s * SUPER + i;
        float a = g_Ac[c * 64 + j], b = g_Bc[c * 64 + j];
        B = fmaf(a, B, b);
        A *= a;
    }
    g_A2[s * 64 + j] = A;
    g_B2[s * 64 + j] = B;
}
__global__ void k2b_super_scan() {         // grid 1, block 64
    const int j = threadIdx.x;
    float u = 0.f;
    #pragma unroll 4
    for (int s = 0; s < NSUPER; s++) {
        g_U2[s * 64 + j] = u;
        u = fmaf(g_A2[s * 64 + j], u, g_B2[s * 64 + j]);
    }
}
__global__ void k2c_expand() {             // grid 64, block 64
    const int s = blockIdx.x, j = threadIdx.x;
    float u = g_U2[s * 64 + j];
    #pragma unroll 4
    for (int i = 0; i < SUPER; i++) {
        int c = s * SUPER + i;
        g_U[c * 64 + j] = u;
        u = fmaf(g_Ac[c * 64 + j], u, g_Bc[c * 64 + j]);
    }
}

// ============================================================================
// k3: load a,b -> parallel replay -> swizzled z tile -> GEMM2 -> out
// smem = 38912 B
// ============================================================================
__global__ __launch_bounds__(256, 4)
void k3_replay_gemm2(const float* __restrict__ W2,
                     const float* __restrict__ B2,
                     float* __restrict__ out) {
    extern __shared__ float sm[];
    float*  zsf   = sm;                          // [0,16384)
    float2* parts = (float2*)(sm + 4096);        // [16384,20480)
    float*  ust   = sm + 5120;                   // [20480,22528)
    u64*    W2d   = (u64*)(sm + 5632);           // [22528,38912)

    const int tid = threadIdx.x, c = blockIdx.x;
    const int ri = tid >> 5, ci = tid & 31;
    const int oc = tid & 31, rp = tid >> 5;
    const int t0 = c * TILE_R;

    #pragma unroll
    for (int p = 0; p < 8; p++) {
        int idx = tid + p * 256;
        float w = W2[idx];
        W2d[idx] = pk2(w, w);
    }
    const float b2 = B2[oc];
    if (c == 0 && tid < 32) out[tid] = B2[tid];     // row 0: z = 0

    // load packed a,b for this thread's 8 rows x channel pair
    float4 ab[8];
    #pragma unroll
    for (int e = 0; e < 8; e++)
        ab[e] = g_ab[(size_t)(t0 + 8 * ri + e) * 32 + ci];

    // per-thread 8-row affine partial (time order)
    float A0 = 1.f, B0 = 0.f, A1 = 1.f, B1v = 0.f;
    #pragma unroll
    for (int e = 0; e < 8; e++) {
        B0  = fmaf(ab[e].x, B0,  ab[e].z);  A0 *= ab[e].x;
        B1v = fmaf(ab[e].y, B1v, ab[e].w);  A1 *= ab[e].y;
    }
    ((float4*)parts)[ri * 32 + ci] = make_float4(A0, B0, A1, B1v);
    __syncthreads();

    // group prefix from precomputed chunk-start state
    if (tid < 64) {
        float u = g_U[c * 64 + tid];
        #pragma unroll
        for (int g = 0; g < 8; g++) {
            ust[g * 64 + tid] = u;
            float2 pp = parts[g * 64 + tid];
            u = fmaf(pp.x, u, pp.y);
        }
    }
    __syncthreads();

    // register replay -> swizzled z tile
    {
        float2 us = *(const float2*)(ust + ri * 64 + 2 * ci);
        float u0 = us.x, u1 = us.y;
        const int j0 = 2 * ci, j1 = 2 * ci + 1;
        #pragma unroll
        for (int e = 0; e < 8; e++) {
            u0 = fmaf(ab[e].x, u0, ab[e].z);
            u1 = fmaf(ab[e].y, u1, ab[e].w);
            int r = 8 * ri + e;
            zsf[(j0 * 16 + ((r >> 2) ^ (j0 & 15))) * 4 + (r & 3)] = u0;
            zsf[(j1 * 16 + ((r >> 2) ^ (j1 & 15))) * 4 + (r & 3)] = u1;
        }
    }
    __syncthreads();

    // GEMM2: 8 rows (4 packed pairs) x 1 out channel per thread
    u64 acc0 = pk2(b2, b2), acc1 = acc0, acc2 = acc0, acc3 = acc0;
    {
        const int rb0 = 2 * rp, rb1 = 2 * rp + 1;
        const float4* zs4 = (const float4*)zsf;
        #pragma unroll 1
        for (int k0 = 0; k0 < 64; k0 += 16) {
            #pragma unroll
            for (int j = 0; j < 16; j++) {
                const int k = k0 + j;
                ulonglong2 zA = *(const ulonglong2*)(zs4 + k * 16 + (rb0 ^ j));
                ulonglong2 zB = *(const ulonglong2*)(zs4 + k * 16 + (rb1 ^ j));
                u64 wd = W2d[k * 32 + oc];
                ffma2(acc0, zA.x, wd); ffma2(acc1, zA.y, wd);
                ffma2(acc2, zB.x, wd); ffma2(acc3, zB.y, wd);
            }
        }
    }
    #pragma unroll
    for (int q = 0; q < 4; q++) {
        u64 a = (q == 0) ? acc0 : (q == 1) ? acc1 : (q == 2) ? acc2 : acc3;
        float2 v = upk(a);
        int t = t0 + 1 + 8 * rp + 2 * q;
        if (t < T_TOTAL)     out[(size_t)t * 32 + oc]       = v.x;
        if (t + 1 < T_TOTAL) out[(size_t)(t + 1) * 32 + oc] = v.y;
    }
}

// ============================================================================
// launch
// ============================================================================
extern "C" void kernel_launch(void* const* d_in, const int* in_sizes, int n_in,
                              void* d_out, int out_size) {
    const float* inp = (const float*)d_in[0];
    const float* W1  = (const float*)d_in[1];
    const float* B1  = (const float*)d_in[2];
    const float* W2  = (const float*)d_in[3];
    const float* B2  = (const float*)d_in[4];
    float* out = (float*)d_out;

    const int smem1 = 53248;
    const int smem3 = 38912;
    cudaFuncSetAttribute(k1_gemm1,       cudaFuncAttributeMaxDynamicSharedMemorySize, smem1);
    cudaFuncSetAttribute(k3_replay_gemm2, cudaFuncAttributeMaxDynamicSharedMemorySize, smem3);

    k1_gemm1<<<K1_BLK, 256, smem1>>>(inp, W1, B1);
    k2a_super_agg<<<NSUPER, 64>>>();
    k2b_super_scan<<<1, 64>>>();
    k2c_expand<<<NSUPER, 64>>>();
    k3_replay_gemm2<<<NCHUNK, 256, smem3>>>(W2, B2, out);
    (void)in_sizes; (void)n_in; (void)out_size;
}

// round 9
// speedup vs baseline: 2.3533x; 1.1518x over previous
#include <cuda_runtime.h>
#include <cstdint>
#include <cstddef>

#define T_TOTAL 524288
#define NCHUNK  8192          // 64-row chunks
#define K1_BLK  4096          // k1: 128 rows (2 tiles) per CTA
#define TILE_R  64
#define SUPER   128           // chunks per super-chunk in k2
#define NSUPER  (NCHUNK / SUPER)
#define SEGC    32            // chunks per segment (4 segments per super)

// packed per-row gate params: {a0,a1,b0,b1} for channel pair ci -> 268MB
__device__ __align__(16) float4 g_ab[(size_t)T_TOTAL * 32];
// per-chunk aggregates and chunk-start states
__device__ __align__(16) float g_Ac[NCHUNK * 64];
__device__ __align__(16) float g_Bc[NCHUNK * 64];
__device__ __align__(16) float g_U [NCHUNK * 64];
__device__ __align__(16) float g_A2[NSUPER * 64];
__device__ __align__(16) float g_B2[NSUPER * 64];
__device__ __align__(16) float g_U2[NSUPER * 64];

typedef unsigned long long u64;

__device__ __forceinline__ u64 pk2(float lo, float hi) {
    u64 r; asm("mov.b64 %0, {%1,%2};" : "=l"(r) : "f"(lo), "f"(hi)); return r;
}
__device__ __forceinline__ float2 upk(u64 v) {
    float2 r; asm("mov.b64 {%0,%1}, %2;" : "=f"(r.x), "=f"(r.y) : "l"(v)); return r;
}
__device__ __forceinline__ void ffma2(u64 &d, u64 a, u64 b) {
    asm("fma.rn.f32x2 %0, %1, %2, %0;" : "+l"(d) : "l"(a), "l"(b));
}
__device__ __forceinline__ float sigf(float x) {
    float e = __expf(-x);
    return __fdividef(1.0f, 1.0f + e);
}

// swizzled transposed x tile: float4 block (k, rb) at k*16 + (rb ^ (k&15))
__device__ __forceinline__ void fill_x(float* xsf, const float* __restrict__ inp,
                                       int t0, int tid) {
    #pragma unroll
    for (int p = 0; p < 4; p++) {
        int i = tid + p * 256;
        int r = i >> 4, c = i & 15;
        float4 v = *(const float4*)(inp + (size_t)(t0 + r) * 64 + 4 * c);
        int rb = r >> 2, r3 = r & 3;
        #pragma unroll
        for (int j = 0; j < 4; j++) {
            int k = 4 * c + j;
            float val = (j == 0) ? v.x : (j == 1) ? v.y : (j == 2) ? v.z : v.w;
            xsf[(k * 16 + (rb ^ (k & 15))) * 4 + r3] = val;
        }
    }
}

// GEMM1 core: 8 rows (4 packed pairs) x 4 channels per thread
__device__ __forceinline__ void gemm1_core(const float4* xs4, const float4* w4,
                                           int ri, int ci,
                                           u64 aL0[4], u64 aL1[4],
                                           u64 aR0[4], u64 aR1[4]) {
    const int rb0 = 2 * ri, rb1 = 2 * ri + 1;
    #pragma unroll
    for (int q = 0; q < 4; q++) { aL0[q]=0ull; aL1[q]=0ull; aR0[q]=0ull; aR1[q]=0ull; }
    #pragma unroll 1
    for (int k0 = 0; k0 < 64; k0 += 16) {
        #pragma unroll
        for (int j = 0; j < 16; j++) {
            const int k = k0 + j;
            ulonglong2 xA = *(const ulonglong2*)(xs4 + k * 16 + (rb0 ^ j));
            ulonglong2 xB = *(const ulonglong2*)(xs4 + k * 16 + (rb1 ^ j));
            float4 wv = w4[k * 32 + ci];
            u64 wl0 = pk2(wv.x, wv.x), wl1 = pk2(wv.y, wv.y);
            u64 wr0 = pk2(wv.z, wv.z), wr1 = pk2(wv.w, wv.w);
            ffma2(aL0[0], xA.x, wl0); ffma2(aL0[1], xA.y, wl0);
            ffma2(aL0[2], xB.x, wl0); ffma2(aL0[3], xB.y, wl0);
            ffma2(aL1[0], xA.x, wl1); ffma2(aL1[1], xA.y, wl1);
            ffma2(aL1[2], xB.x, wl1); ffma2(aL1[3], xB.y, wl1);
            ffma2(aR0[0], xA.x, wr0); ffma2(aR0[1], xA.y, wr0);
            ffma2(aR0[2], xB.x, wr0); ffma2(aR0[3], xB.y, wr0);
            ffma2(aR1[0], xA.x, wr1); ffma2(aR1[1], xA.y, wr1);
            ffma2(aR1[2], xB.x, wr1); ffma2(aR1[3], xB.y, wr1);
        }
    }
}

__device__ __forceinline__ void build_w1i(float4* W1i4, const float* __restrict__ W1, int tid) {
    #pragma unroll
    for (int p = 0; p < 8; p++) {
        int idx = tid + p * 256;
        int k = idx >> 5, cc = idx & 31;
        float2 l = *(const float2*)(W1 + k * 128 + 2 * cc);
        float2 r = *(const float2*)(W1 + k * 128 + 64 + 2 * cc);
        W1i4[idx] = make_float4(l.x, l.y, r.x, r.y);
    }
}

// ============================================================================
// k1: GEMM1 + gate -> g_ab (packed) + per-64-row-chunk aggregates
// ============================================================================
__global__ __launch_bounds__(256, 3)
void k1_gemm1(const float* __restrict__ inp,
              const float* __restrict__ W1,
              const float* __restrict__ B1) {
    extern __shared__ float sm[];
    float4* W1i4  = (float4*)sm;                 // [0,32768)
    float*  xsf   = sm + 8192;                   // [32768,49152)
    float2* parts = (float2*)(sm + 12288);       // [49152,53248)

    const int tid = threadIdx.x, c = blockIdx.x;
    const int ri = tid >> 5, ci = tid & 31;

    build_w1i(W1i4, W1, tid);
    const float bl0 = B1[2 * ci],      bl1 = B1[2 * ci + 1];
    const float br0 = B1[64 + 2 * ci], br1 = B1[64 + 2 * ci + 1];
    __syncthreads();

    #pragma unroll 1
    for (int tt = 0; tt < 2; tt++) {
        const int chunk = 2 * c + tt;
        const int t0 = chunk * TILE_R;
        fill_x(xsf, inp, t0, tid);
        __syncthreads();

        u64 aL0[4], aL1[4], aR0[4], aR1[4];
        gemm1_core((const float4*)xsf, W1i4, ri, ci, aL0, aL1, aR0, aR1);

        float A0 = 1.f, B0 = 0.f, A1 = 1.f, B1v = 0.f;
        #pragma unroll
        for (int p2 = 0; p2 < 4; p2++) {
            float2 L0 = upk(aL0[p2]), L1 = upk(aL1[p2]);
            float2 R0 = upk(aR0[p2]), R1 = upk(aR1[p2]);
            #pragma unroll
            for (int e = 0; e < 2; e++) {
                int r = 8 * ri + 2 * p2 + e;
                float l0 = sigf((e ? L0.y : L0.x) + bl0);
                float l1 = sigf((e ? L1.y : L1.x) + bl1);
                float r0 = sigf((e ? R0.y : R0.x) + br0);
                float r1 = sigf((e ? R1.y : R1.x) + br1);
                float a0 = l0 * r0, b0 = 1.f - l0;
                float a1 = l1 * r1, b1 = 1.f - l1;
                g_ab[(size_t)(t0 + r) * 32 + ci] = make_float4(a0, a1, b0, b1);
                B0  = fmaf(a0, B0, b0);  A0 *= a0;
                B1v = fmaf(a1, B1v, b1); A1 *= a1;
            }
        }
        ((float4*)parts)[ri * 32 + ci] = make_float4(A0, B0, A1, B1v);
        __syncthreads();

        if (tid < 64) {
            float Ac = 1.f, Bc = 0.f;
            #pragma unroll
            for (int g = 0; g < 8; g++) {
                float2 pp = parts[g * 64 + tid];
                Bc = fmaf(pp.x, Bc, pp.y);
                Ac *= pp.x;
            }
            g_Ac[chunk * 64 + tid] = Ac;
            g_Bc[chunk * 64 + tid] = Bc;
        }
        __syncthreads();
    }
}

// ============================================================================
// k2a: super aggregates — 4 segments x 64 channels per CTA, prefetched
// ============================================================================
__global__ __launch_bounds__(256, 8)
void k2a_super_agg() {
    __shared__ float2 parts[4 * 64];
    const int s = blockIdx.x;
    const int j = threadIdx.x & 63, seg = threadIdx.x >> 6;
    const int base = s * SUPER + seg * SEGC;

    float A = 1.f, B = 0.f;
    #pragma unroll 1
    for (int bq = 0; bq < SEGC / 8; bq++) {
        float a_[8], b_[8];
        #pragma unroll
        for (int i = 0; i < 8; i++) {
            a_[i] = g_Ac[(base + bq * 8 + i) * 64 + j];
            b_[i] = g_Bc[(base + bq * 8 + i) * 64 + j];
        }
        #pragma unroll
        for (int i = 0; i < 8; i++) { B = fmaf(a_[i], B, b_[i]); A *= a_[i]; }
    }
    parts[seg * 64 + j] = make_float2(A, B);
    __syncthreads();

    if (threadIdx.x < 64) {
        float As = 1.f, Bs = 0.f;
        #pragma unroll
        for (int g = 0; g < 4; g++) {
            float2 pp = parts[g * 64 + threadIdx.x];
            Bs = fmaf(pp.x, Bs, pp.y);
            As *= pp.x;
        }
        g_A2[s * 64 + threadIdx.x] = As;
        g_B2[s * 64 + threadIdx.x] = Bs;
    }
}

// ============================================================================
// k2b: scan over 64 supers, prefetched in batches of 16
// ============================================================================
__global__ void k2b_super_scan() {
    const int j = threadIdx.x;
    float u = 0.f;
    #pragma unroll 1
    for (int bq = 0; bq < NSUPER / 16; bq++) {
        float A_[16], B_[16];
        #pragma unroll
        for (int i = 0; i < 16; i++) {
            A_[i] = g_A2[(bq * 16 + i) * 64 + j];
            B_[i] = g_B2[(bq * 16 + i) * 64 + j];
        }
        #pragma unroll
        for (int i = 0; i < 16; i++) {
            g_U2[(bq * 16 + i) * 64 + j] = u;
            u = fmaf(A_[i], u, B_[i]);
        }
    }
}

// ============================================================================
// k2c: expand to chunk-start states — segmented + prefetched
// ============================================================================
__global__ __launch_bounds__(256, 8)
void k2c_expand() {
    __shared__ float2 parts[4 * 64];
    __shared__ float  segu [4 * 64];
    const int s = blockIdx.x;
    const int j = threadIdx.x & 63, seg = threadIdx.x >> 6;
    const int base = s * SUPER + seg * SEGC;

    // phase 1: segment aggregates
    float A = 1.f, B = 0.f;
    #pragma unroll 1
    for (int bq = 0; bq < SEGC / 8; bq++) {
        float a_[8], b_[8];
        #pragma unroll
        for (int i = 0; i < 8; i++) {
            a_[i] = g_Ac[(base + bq * 8 + i) * 64 + j];
            b_[i] = g_Bc[(base + bq * 8 + i) * 64 + j];
        }
        #pragma unroll
        for (int i = 0; i < 8; i++) { B = fmaf(a_[i], B, b_[i]); A *= a_[i]; }
    }
    parts[seg * 64 + j] = make_float2(A, B);
    __syncthreads();

    // phase 2: segment-start states from super-start
    if (threadIdx.x < 64) {
        float u = g_U2[s * 64 + threadIdx.x];
        #pragma unroll
        for (int g = 0; g < 4; g++) {
            segu[g * 64 + threadIdx.x] = u;
            float2 pp = parts[g * 64 + threadIdx.x];
            u = fmaf(pp.x, u, pp.y);
        }
    }
    __syncthreads();

    // phase 3: expand within segment
    float u = segu[seg * 64 + j];
    #pragma unroll 1
    for (int bq = 0; bq < SEGC / 8; bq++) {
        float a_[8], b_[8];
        #pragma unroll
        for (int i = 0; i < 8; i++) {
            a_[i] = g_Ac[(base + bq * 8 + i) * 64 + j];
            b_[i] = g_Bc[(base + bq * 8 + i) * 64 + j];
        }
        #pragma unroll
        for (int i = 0; i < 8; i++) {
            g_U[(base + bq * 8 + i) * 64 + j] = u;
            u = fmaf(a_[i], u, b_[i]);
        }
    }
}

// ============================================================================
// k3: load a,b -> parallel replay -> swizzled z tile -> GEMM2 -> out
// ============================================================================
__global__ __launch_bounds__(256, 4)
void k3_replay_gemm2(const float* __restrict__ W2,
                     const float* __restrict__ B2,
                     float* __restrict__ out) {
    extern __shared__ float sm[];
    float*  zsf   = sm;                          // [0,16384)
    float2* parts = (float2*)(sm + 4096);        // [16384,20480)
    float*  ust   = sm + 5120;                   // [20480,22528)
    u64*    W2d   = (u64*)(sm + 5632);           // [22528,38912)

    const int tid = threadIdx.x, c = blockIdx.x;
    const int ri = tid >> 5, ci = tid & 31;
    const int oc = tid & 31, rp = tid >> 5;
    const int t0 = c * TILE_R;

    #pragma unroll
    for (int p = 0; p < 8; p++) {
        int idx = tid + p * 256;
        float w = W2[idx];
        W2d[idx] = pk2(w, w);
    }
    const float b2 = B2[oc];
    if (c == 0 && tid < 32) out[tid] = B2[tid];

    float4 ab[8];
    #pragma unroll
    for (int e = 0; e < 8; e++)
        ab[e] = g_ab[(size_t)(t0 + 8 * ri + e) * 32 + ci];

    float A0 = 1.f, B0 = 0.f, A1 = 1.f, B1v = 0.f;
    #pragma unroll
    for (int e = 0; e < 8; e++) {
        B0  = fmaf(ab[e].x, B0,  ab[e].z);  A0 *= ab[e].x;
        B1v = fmaf(ab[e].y, B1v, ab[e].w);  A1 *= ab[e].y;
    }
    ((float4*)parts)[ri * 32 + ci] = make_float4(A0, B0, A1, B1v);
    __syncthreads();

    if (tid < 64) {
        float u = g_U[c * 64 + tid];
        #pragma unroll
        for (int g = 0; g < 8; g++) {
            ust[g * 64 + tid] = u;
            float2 pp = parts[g * 64 + tid];
            u = fmaf(pp.x, u, pp.y);
        }
    }
    __syncthreads();

    {
        float2 us = *(const float2*)(ust + ri * 64 + 2 * ci);
        float u0 = us.x, u1 = us.y;
        const int j0 = 2 * ci, j1 = 2 * ci + 1;
        #pragma unroll
        for (int e = 0; e < 8; e++) {
            u0 = fmaf(ab[e].x, u0, ab[e].z);
            u1 = fmaf(ab[e].y, u1, ab[e].w);
            int r = 8 * ri + e;
            zsf[(j0 * 16 + ((r >> 2) ^ (j0 & 15))) * 4 + (r & 3)] = u0;
            zsf[(j1 * 16 + ((r >> 2) ^ (j1 & 15))) * 4 + (r & 3)] = u1;
        }
    }
    __syncthreads();

    u64 acc0 = pk2(b2, b2), acc1 = acc0, acc2 = acc0, acc3 = acc0;
    {
        const int rb0 = 2 * rp, rb1 = 2 * rp + 1;
        const float4* zs4 = (const float4*)zsf;
        #pragma unroll 1
        for (int k0 = 0; k0 < 64; k0 += 16) {
            #pragma unroll
            for (int j = 0; j < 16; j++) {
                const int k = k0 + j;
                ulonglong2 zA = *(const ulonglong2*)(zs4 + k * 16 + (rb0 ^ j));
                ulonglong2 zB = *(const ulonglong2*)(zs4 + k * 16 + (rb1 ^ j));
                u64 wd = W2d[k * 32 + oc];
                ffma2(acc0, zA.x, wd); ffma2(acc1, zA.y, wd);
                ffma2(acc2, zB.x, wd); ffma2(acc3, zB.y, wd);
            }
        }
    }
    #pragma unroll
    for (int q = 0; q < 4; q++) {
        u64 a = (q == 0) ? acc0 : (q == 1) ? acc1 : (q == 2) ? acc2 : acc3;
        float2 v = upk(a);
        int t = t0 + 1 + 8 * rp + 2 * q;
        if (t < T_TOTAL)     out[(size_t)t * 32 + oc]       = v.x;
        if (t + 1 < T_TOTAL) out[(size_t)(t + 1) * 32 + oc] = v.y;
    }
}

// ============================================================================
// launch
// ============================================================================
extern "C" void kernel_launch(void* const* d_in, const int* in_sizes, int n_in,
                              void* d_out, int out_size) {
    const float* inp = (const float*)d_in[0];
    const float* W1  = (const float*)d_in[1];
    const float* B1  = (const float*)d_in[2];
    const float* W2  = (const float*)d_in[3];
    const float* B2  = (const float*)d_in[4];
    float* out = (float*)d_out;

    const int smem1 = 53248;
    const int smem3 = 38912;
    cudaFuncSetAttribute(k1_gemm1,        cudaFuncAttributeMaxDynamicSharedMemorySize, smem1);
    cudaFuncSetAttribute(k3_replay_gemm2, cudaFuncAttributeMaxDynamicSharedMemorySize, smem3);

    k1_gemm1<<<K1_BLK, 256, smem1>>>(inp, W1, B1);
    k2a_super_agg<<<NSUPER, 256>>>();
    k2b_super_scan<<<1, 64>>>();
    k2c_expand<<<NSUPER, 256>>>();
    k3_replay_gemm2<<<NCHUNK, 256, smem3>>>(W2, B2, out);
    (void)in_sizes; (void)n_in; (void)out_size;
}